// round 1
// baseline (speedup 1.0000x reference)
#include <cuda_runtime.h>
#include <math.h>

// Problem constants
#define BATCH   8
#define SEQ     2048
#define DMODEL  1024
#define DSPACE  64
#define N_QK    512
#define N_V     256
#define N_REL   128
#define N_VAL   32
#define N_TOT   928          // used neurons (know slice unused)
#define K_QK    64
#define K_V     32
#define K_REL   16
#define K_VAL   3

#define TPB     64           // tokens per block
#define NTHREADS 256
#define BLOCKS_PER_BATCH (SEQ / TPB)   // 32

// Output layout (all float32, concatenated in reference return order)
#define OFF_IDXQK 0                       // 8*64
#define OFF_IDXV  (OFF_IDXQK + BATCH*K_QK)        // 512
#define OFF_RWQ   (OFF_IDXV  + BATCH*K_V)         // 768
#define OFF_RWK   (OFF_RWQ   + BATCH*N_REL)       // 1792
#define OFF_VW    (OFF_RWK   + BATCH*N_REL)       // 2816
#define OFF_WQK   (OFF_VW    + BATCH*N_VAL)       // 3072
#define OFF_WV    (OFF_WQK   + BATCH*N_QK)        // 7168

// Scratch (device globals: no allocation allowed)
__device__ float g_embT[DSPACE * N_TOT];   // normalized emb, transposed [d][n]
__device__ float g_w[BATCH * N_TOT];       // routed weights

// Shared memory layout (floats):
//  U region (36864 fl):
//    phase A: Xs[256][65] (16640) | Ws[256][64] (16384)
//    phase B: embS[64][<=512] (<=32768) | eS[4096] at +32768
//  Hs[64][65] at 36864 (4160)
//  w_local[928] at 41024
//  impS[64] at 41952
//  redS[256] at 42016
//  alphaS[64] at 42272
#define SMEM_FLOATS 42336
#define SMEM_BYTES  (SMEM_FLOATS * 4)

__global__ void zero_w_kernel() {
    int i = blockIdx.x * blockDim.x + threadIdx.x;
    if (i < BATCH * N_TOT) g_w[i] = 0.0f;
}

// Normalize neuron embeddings (first 928 rows), store transposed [d][n]
__global__ void prep_kernel(const float* __restrict__ emb) {
    int r = blockIdx.x;     // neuron
    int t = threadIdx.x;    // dim 0..63
    __shared__ float s[64];
    float v = emb[r * DSPACE + t];
    s[t] = v * v;
    __syncthreads();
    #pragma unroll
    for (int o = 32; o > 0; o >>= 1) {
        if (t < o) s[t] += s[t + o];
        __syncthreads();
    }
    float norm = sqrtf(s[0]);
    g_embT[t * N_TOT + r] = v / norm;
}

__global__ void __launch_bounds__(NTHREADS)
main_kernel(const float* __restrict__ x, const float* __restrict__ imp,
            const float* __restrict__ Wm, const float* __restrict__ bias)
{
    extern __shared__ float sm[];
    float* U      = sm;
    float* Xs     = U;                 // [256][65]
    float* Ws     = U + 16640;         // [256][64]
    float* embS   = U;                 // [64][n]
    float* eS     = U + 32768;         // [4096]
    float* Hs     = sm + 36864;        // [64][65]
    float* w_local= sm + 41024;        // [928]
    float* impS   = sm + 41952;        // [64]
    float* redS   = sm + 42016;        // [256]
    float* alphaS = sm + 42272;        // [64]

    const int tid = threadIdx.x;
    const int bb  = blockIdx.x / BLOCKS_PER_BATCH;
    const int s0  = (blockIdx.x % BLOCKS_PER_BATCH) * TPB;

    for (int i = tid; i < N_TOT; i += NTHREADS) w_local[i] = 0.0f;
    if (tid < TPB) impS[tid] = imp[bb * SEQ + s0 + tid];

    // ---------------- GEMM1: H[64][64] = X[64][1024] @ W[1024][64] + b ----------------
    const int ty = tid >> 4;      // 0..15 -> token rows ty*4..ty*4+3
    const int tx = tid & 15;      // 0..15 -> cols tx*4..tx*4+3
    float acc[4][4];
    #pragma unroll
    for (int r = 0; r < 4; r++)
        #pragma unroll
        for (int c = 0; c < 4; c++) acc[r][c] = 0.0f;

    const float* xbase = x + (size_t)(bb * SEQ + s0) * DMODEL;
    for (int p = 0; p < 4; p++) {
        __syncthreads();
        // load Xs transposed: Xs[d][t], thread owns d = tid
        {
            const float* xp = xbase + p * 256 + tid;
            float* xrow = Xs + tid * 65;
            #pragma unroll 8
            for (int t = 0; t < TPB; t++) xrow[t] = xp[(size_t)t * DMODEL];
        }
        // load Ws[256][64] via float4 (contiguous chunk of W)
        {
            const float4* w4 = reinterpret_cast<const float4*>(Wm + p * 256 * DSPACE);
            float4* ws4 = reinterpret_cast<float4*>(Ws);
            #pragma unroll
            for (int k = 0; k < 16; k++) ws4[tid + k * 256] = w4[tid + k * 256];
        }
        __syncthreads();
        #pragma unroll 4
        for (int d = 0; d < 256; d++) {
            float4 b4 = reinterpret_cast<const float4*>(Ws)[d * 16 + tx];
            float a0 = Xs[d * 65 + ty * 4 + 0];
            float a1 = Xs[d * 65 + ty * 4 + 1];
            float a2 = Xs[d * 65 + ty * 4 + 2];
            float a3 = Xs[d * 65 + ty * 4 + 3];
            acc[0][0] += a0 * b4.x; acc[0][1] += a0 * b4.y; acc[0][2] += a0 * b4.z; acc[0][3] += a0 * b4.w;
            acc[1][0] += a1 * b4.x; acc[1][1] += a1 * b4.y; acc[1][2] += a1 * b4.z; acc[1][3] += a1 * b4.w;
            acc[2][0] += a2 * b4.x; acc[2][1] += a2 * b4.y; acc[2][2] += a2 * b4.z; acc[2][3] += a2 * b4.w;
            acc[3][0] += a3 * b4.x; acc[3][1] += a3 * b4.y; acc[3][2] += a3 * b4.z; acc[3][3] += a3 * b4.w;
        }
    }
    // bias + write Hs[t][d]
    {
        float bc[4];
        #pragma unroll
        for (int c = 0; c < 4; c++) bc[c] = bias[tx * 4 + c];
        #pragma unroll
        for (int r = 0; r < 4; r++)
            #pragma unroll
            for (int c = 0; c < 4; c++)
                Hs[(ty * 4 + r) * 65 + tx * 4 + c] = acc[r][c] + bc[c];
    }

    // ---------------- GEMM2 + per-slice softmax + importance reduction ----------------
    const int sliceLo[4] = {0, N_QK, N_QK + N_V, N_QK + N_V + N_REL};
    const int sliceN[4]  = {N_QK, N_V, N_REL, N_VAL};

    for (int sl = 0; sl < 4; sl++) {
        const int lo = sliceLo[sl];
        const int n  = sliceN[sl];
        __syncthreads();   // U region reuse safe
        // load embS[d][n]
        for (int i = tid; i < DSPACE * n; i += NTHREADS) {
            int d = i / n, nn = i - d * n;
            embS[i] = g_embT[d * N_TOT + lo + nn];
        }
        __syncthreads();

        int TG = 4096 / n; if (TG > TPB) TG = TPB;   // tokens per group
        const int nq_cnt = n >> 2;
        const int nq = tid % nq_cnt;
        const int q  = tid / nq_cnt;
        const bool active = (q * 4 < TG);
        const int tpt  = NTHREADS / TG;   // reduction threads per token
        const int kcnt = n / tpt;

        for (int t0 = 0; t0 < TPB; t0 += TG) {
            if (active) {
                float acc2[4][4];
                #pragma unroll
                for (int r = 0; r < 4; r++)
                    #pragma unroll
                    for (int c = 0; c < 4; c++) acc2[r][c] = 0.0f;
                const int tbase = (t0 + q * 4) * 65;
                #pragma unroll 4
                for (int d = 0; d < DSPACE; d++) {
                    float4 e4 = reinterpret_cast<const float4*>(embS)[d * nq_cnt + nq];
                    float h0 = Hs[tbase + 0 * 65 + d];
                    float h1 = Hs[tbase + 1 * 65 + d];
                    float h2 = Hs[tbase + 2 * 65 + d];
                    float h3 = Hs[tbase + 3 * 65 + d];
                    acc2[0][0] += h0 * e4.x; acc2[0][1] += h0 * e4.y; acc2[0][2] += h0 * e4.z; acc2[0][3] += h0 * e4.w;
                    acc2[1][0] += h1 * e4.x; acc2[1][1] += h1 * e4.y; acc2[1][2] += h1 * e4.z; acc2[1][3] += h1 * e4.w;
                    acc2[2][0] += h2 * e4.x; acc2[2][1] += h2 * e4.y; acc2[2][2] += h2 * e4.z; acc2[2][3] += h2 * e4.w;
                    acc2[3][0] += h3 * e4.x; acc2[3][1] += h3 * e4.y; acc2[3][2] += h3 * e4.z; acc2[3][3] += h3 * e4.w;
                }
                // exp (logits are small; no max-subtraction needed for fp32 range)
                #pragma unroll
                for (int r = 0; r < 4; r++)
                    #pragma unroll
                    for (int c = 0; c < 4; c++)
                        eS[(q * 4 + r) * n + nq * 4 + c] = expf(acc2[r][c]);
            }
            __syncthreads();
            // per-token sums
            {
                const int i0 = tid % tpt, tt = tid / tpt;
                float part = 0.0f;
                for (int k = 0; k < kcnt; k++) part += eS[tt * n + i0 + k * tpt];
                redS[tid] = part;
            }
            __syncthreads();
            if (tid < TG) {
                float ssum = 0.0f;
                for (int i0 = 0; i0 < tpt; i0++) ssum += redS[tid * tpt + i0];
                alphaS[tid] = impS[t0 + tid] / ssum;
            }
            __syncthreads();
            // w_local[nn] += sum_t alpha_t * e[t][nn]
            for (int nn = tid; nn < n; nn += NTHREADS) {
                float s = 0.0f;
                for (int tt = 0; tt < TG; tt++) s += alphaS[tt] * eS[tt * n + nn];
                w_local[lo + nn] += s;
            }
            __syncthreads();
        }
    }

    for (int i = tid; i < N_TOT; i += NTHREADS)
        atomicAdd(&g_w[bb * N_TOT + i], w_local[i]);
}

// Per-batch top-k / sparsify / output assembly
__global__ void final_kernel(float* __restrict__ out) {
    const int b = blockIdx.x;
    const int tid = threadIdx.x;
    __shared__ float ws[N_TOT];
    __shared__ int flag[N_QK];

    for (int i = tid; i < N_TOT; i += 256) ws[i] = g_w[b * N_TOT + i];
    __syncthreads();

    // raw w copies
    for (int i = tid; i < N_QK; i += 256) out[OFF_WQK + b * N_QK + i] = ws[i];
    for (int i = tid; i < N_V;  i += 256) out[OFF_WV  + b * N_V  + i] = ws[N_QK + i];

    // ---- task 1: qk top-64 indices (ascending) ----
    {
        const int lo = 0, n = N_QK, K = K_QK;
        for (int i = tid; i < n; i += 256) {
            float wi = ws[lo + i]; int r = 0;
            for (int j = 0; j < n; j++) {
                float wj = ws[lo + j];
                r += (wj > wi) || (wj == wi && j < i);
            }
            flag[i] = (r < K) ? 1 : 0;
        }
        __syncthreads();
        for (int i = tid; i < n; i += 256) {
            if (flag[i]) {
                int pos = 0;
                for (int j = 0; j < i; j++) pos += flag[j];
                out[OFF_IDXQK + b * K + pos] = (float)i;
            }
        }
        __syncthreads();
    }
    // ---- task 2: v top-32 indices (ascending) ----
    {
        const int lo = N_QK, n = N_V, K = K_V;
        for (int i = tid; i < n; i += 256) {
            float wi = ws[lo + i]; int r = 0;
            for (int j = 0; j < n; j++) {
                float wj = ws[lo + j];
                r += (wj > wi) || (wj == wi && j < i);
            }
            flag[i] = (r < K) ? 1 : 0;
        }
        __syncthreads();
        for (int i = tid; i < n; i += 256) {
            if (flag[i]) {
                int pos = 0;
                for (int j = 0; j < i; j++) pos += flag[j];
                out[OFF_IDXV + b * K + pos] = (float)i;
            }
        }
        __syncthreads();
    }
    // ---- task 3: rel sparsify top-16 (rw_Q == rw_K) ----
    {
        const int lo = N_QK + N_V, n = N_REL, K = K_REL;
        for (int i = tid; i < n; i += 256) {
            float wi = ws[lo + i]; int r = 0;
            for (int j = 0; j < n; j++) {
                float wj = ws[lo + j];
                r += (wj > wi) || (wj == wi && j < i);
            }
            float v = (r < K) ? wi : 0.0f;
            out[OFF_RWQ + b * n + i] = v;
            out[OFF_RWK + b * n + i] = v;
        }
        __syncthreads();
    }
    // ---- task 4: val sparsify top-3 ----
    {
        const int lo = N_QK + N_V + N_REL, n = N_VAL, K = K_VAL;
        for (int i = tid; i < n; i += 256) {
            float wi = ws[lo + i]; int r = 0;
            for (int j = 0; j < n; j++) {
                float wj = ws[lo + j];
                r += (wj > wi) || (wj == wi && j < i);
            }
            out[OFF_VW + b * n + i] = (r < K) ? wi : 0.0f;
        }
    }
}

extern "C" void kernel_launch(void* const* d_in, const int* in_sizes, int n_in,
                              void* d_out, int out_size) {
    const float* x    = (const float*)d_in[0];
    const float* imp  = (const float*)d_in[1];
    const float* Wm   = (const float*)d_in[2];
    const float* bias = (const float*)d_in[3];
    const float* emb  = (const float*)d_in[4];
    float* out = (float*)d_out;

    cudaFuncSetAttribute(main_kernel, cudaFuncAttributeMaxDynamicSharedMemorySize, SMEM_BYTES);

    zero_w_kernel<<<(BATCH * N_TOT + 255) / 256, 256>>>();
    prep_kernel<<<N_TOT, 64>>>(emb);
    main_kernel<<<BATCH * BLOCKS_PER_BATCH, NTHREADS, SMEM_BYTES>>>(x, imp, Wm, bias);
    final_kernel<<<BATCH, 256>>>(out);
}

// round 2
// speedup vs baseline: 1.8854x; 1.8854x over previous
#include <cuda_runtime.h>
#include <math.h>

typedef unsigned long long ull;

// Problem constants
#define BATCH   8
#define SEQ     2048
#define DMODEL  1024
#define DSPACE  64
#define N_QK    512
#define N_V     256
#define N_REL   128
#define N_VAL   32
#define N_TOT   928
#define K_QK    64
#define K_V     32
#define K_REL   16
#define K_VAL   3

#define TPB      128                      // tokens per block
#define NTHREADS 128
#define NBLOCKS  (BATCH * SEQ / TPB)      // 128

// Output layout (float32, reference return order)
#define OFF_IDXQK 0
#define OFF_IDXV  (OFF_IDXQK + BATCH*K_QK)
#define OFF_RWQ   (OFF_IDXV  + BATCH*K_V)
#define OFF_RWK   (OFF_RWQ   + BATCH*N_REL)
#define OFF_VW    (OFF_RWK   + BATCH*N_REL)
#define OFF_WQK   (OFF_VW    + BATCH*N_VAL)
#define OFF_WV    (OFF_WQK   + BATCH*N_QK)

// Shared memory byte offsets
// U region (embS overlaps XsP+Ws): 131072 B
//   XsP: ull[64 token-pairs][130]  (66560 B)
//   Ws : float[128][64] at +66560  (32768 B)
//   embS: float[64][<=512]         (<=131072 B)
// HsP: ull[64 tp][66] at 131072    (33792 B)
// w_local: float[928] at 164864
// impS: float[128] at 168576
// partS: float[256] at 169088
// alphaS: float[128] at 170112
#define SM_HSP   131072
#define SM_WL    164864
#define SM_IMP   168576
#define SM_PART  169088
#define SM_ALPHA 170112
#define SMEM_BYTES 170624

#define XSP_STRIDE 130
#define HSP_STRIDE 66

// device scratch (no allocation allowed)
__device__ float g_embT[DSPACE * N_TOT];   // normalized emb transposed [d][n]
__device__ float g_w[BATCH * N_TOT];

// ---------------- f32x2 helpers ----------------
__device__ __forceinline__ ull d_pack(float x, float y) {
    ull r; asm("mov.b64 %0, {%1, %2};" : "=l"(r) : "f"(x), "f"(y)); return r;
}
__device__ __forceinline__ ull d_dup(float x) {
    ull r; asm("mov.b64 %0, {%1, %1};" : "=l"(r) : "f"(x)); return r;
}
__device__ __forceinline__ void d_unpack(ull v, float& x, float& y) {
    asm("mov.b64 {%0, %1}, %2;" : "=f"(x), "=f"(y) : "l"(v));
}
__device__ __forceinline__ ull d_fma2(ull a, ull b, ull c) {
    ull d; asm("fma.rn.f32x2 %0, %1, %2, %3;" : "=l"(d) : "l"(a), "l"(b), "l"(c)); return d;
}
__device__ __forceinline__ ull d_add2(ull a, ull b) {
    ull d; asm("add.rn.f32x2 %0, %1, %2;" : "=l"(d) : "l"(a), "l"(b)); return d;
}

// ---------------- small prep kernels ----------------
__global__ void zero_w_kernel() {
    int i = blockIdx.x * blockDim.x + threadIdx.x;
    if (i < BATCH * N_TOT) g_w[i] = 0.0f;
}

__global__ void prep_kernel(const float* __restrict__ emb) {
    int r = blockIdx.x;
    int t = threadIdx.x;
    __shared__ float s[64];
    float v = emb[r * DSPACE + t];
    s[t] = v * v;
    __syncthreads();
    #pragma unroll
    for (int o = 32; o > 0; o >>= 1) {
        if (t < o) s[t] += s[t + o];
        __syncthreads();
    }
    float norm = sqrtf(s[0]);
    g_embT[t * N_TOT + r] = v / norm;
}

// ---------------- GEMM2 + softmax + routed-weight slice ----------------
template<int N, int LO>
__device__ __forceinline__ void do_slice(char* sm, int tid) {
    float* embS   = (float*)sm;
    ull*   HsP    = (ull*)(sm + SM_HSP);
    float* w_local= (float*)(sm + SM_WL);
    float* impS   = (float*)(sm + SM_IMP);
    float* partS  = (float*)(sm + SM_PART);
    float* alphaS = (float*)(sm + SM_ALPHA);

    constexpr int NQ  = N / 8;                              // threads along n
    constexpr int LNQ = (NQ==64)?6:(NQ==32)?5:(NQ==16)?4:2;
    constexpr int TG0 = 1024 / NQ;                          // tokens per pass (8 per q)
    constexpr int TG  = (TG0 > 128) ? 128 : TG0;
    constexpr int W   = (NQ < 32) ? NQ : 32;                // shuffle width

    const int nq = tid & (NQ - 1);
    const int q  = tid >> LNQ;
    const bool active = (q * 8 < TG);

    __syncthreads();
    {
        constexpr int NF4 = N / 4;
        for (int i = tid; i < 64 * NF4; i += NTHREADS) {
            int d = i / NF4, c = i - d * NF4;
            ((float4*)embS)[i] = *(const float4*)(g_embT + (size_t)d * N_TOT + LO + c * 4);
        }
    }
    __syncthreads();

    float wacc[8];
    #pragma unroll
    for (int j = 0; j < 8; j++) wacc[j] = 0.0f;

    for (int t0 = 0; t0 < TPB; t0 += TG) {
        float el[4][8], eh[4][8];
        float ps[8];
        if (active) {
            ull acc[4][8];
            #pragma unroll
            for (int u = 0; u < 4; u++)
                #pragma unroll
                for (int j = 0; j < 8; j++) acc[u][j] = 0ull;

            const ull* hrow = HsP + (size_t)(t0 / 2 + q * 4) * HSP_STRIDE;
            const float4* eb4 = (const float4*)embS;
            #pragma unroll 4
            for (int d = 0; d < DSPACE; d++) {
                float4 b0 = eb4[d * (N / 4) + nq * 2];
                float4 b1 = eb4[d * (N / 4) + nq * 2 + 1];
                ull bd[8];
                bd[0]=d_dup(b0.x); bd[1]=d_dup(b0.y); bd[2]=d_dup(b0.z); bd[3]=d_dup(b0.w);
                bd[4]=d_dup(b1.x); bd[5]=d_dup(b1.y); bd[6]=d_dup(b1.z); bd[7]=d_dup(b1.w);
                ull a0 = hrow[d];
                ull a1 = hrow[HSP_STRIDE + d];
                ull a2 = hrow[2*HSP_STRIDE + d];
                ull a3 = hrow[3*HSP_STRIDE + d];
                #pragma unroll
                for (int j = 0; j < 8; j++) {
                    acc[0][j] = d_fma2(a0, bd[j], acc[0][j]);
                    acc[1][j] = d_fma2(a1, bd[j], acc[1][j]);
                    acc[2][j] = d_fma2(a2, bd[j], acc[2][j]);
                    acc[3][j] = d_fma2(a3, bd[j], acc[3][j]);
                }
            }
            // exp + per-token partial sums
            #pragma unroll
            for (int u = 0; u < 4; u++) {
                float sx = 0.0f, sy = 0.0f;
                #pragma unroll
                for (int j = 0; j < 8; j++) {
                    float lo, hi;
                    d_unpack(acc[u][j], lo, hi);
                    float e0 = __expf(lo), e1 = __expf(hi);
                    el[u][j] = e0; eh[u][j] = e1;
                    sx += e0; sy += e1;
                }
                ps[2*u] = sx; ps[2*u+1] = sy;
            }
            // segment reduce over nq
            #pragma unroll
            for (int tt = 0; tt < 8; tt++)
                #pragma unroll
                for (int o = W >> 1; o > 0; o >>= 1)
                    ps[tt] += __shfl_xor_sync(0xffffffffu, ps[tt], o);
            if (NQ == 64) {
                if ((tid & 31) == 0) {
                    int half = (tid >> 5) & 1;
                    #pragma unroll
                    for (int tt = 0; tt < 8; tt++) partS[(q*8+tt)*2 + half] = ps[tt];
                }
            } else {
                if (nq == 0) {
                    #pragma unroll
                    for (int tt = 0; tt < 8; tt++) {
                        partS[(q*8+tt)*2]     = ps[tt];
                        partS[(q*8+tt)*2 + 1] = 0.0f;
                    }
                }
            }
        }
        __syncthreads();
        if (tid < TG) alphaS[tid] = impS[t0 + tid] / (partS[2*tid] + partS[2*tid+1]);
        __syncthreads();
        if (active) {
            #pragma unroll
            for (int u = 0; u < 4; u++) {
                float al = alphaS[q*8 + 2*u];
                float ah = alphaS[q*8 + 2*u + 1];
                #pragma unroll
                for (int j = 0; j < 8; j++)
                    wacc[j] += al * el[u][j] + ah * eh[u][j];
            }
        }
    }
    if (active) {
        #pragma unroll
        for (int j = 0; j < 8; j++)
            atomicAdd(&w_local[LO + nq*8 + j], wacc[j]);
    }
}

// ---------------- main fused kernel ----------------
__global__ void __launch_bounds__(NTHREADS)
main_kernel(const float* __restrict__ x, const float* __restrict__ imp,
            const float* __restrict__ Wm, const float* __restrict__ bias)
{
    extern __shared__ char sm[];
    ull*   XsP    = (ull*)sm;
    float* Ws     = (float*)(sm + 66560);
    ull*   HsP    = (ull*)(sm + SM_HSP);
    float* w_local= (float*)(sm + SM_WL);
    float* impS   = (float*)(sm + SM_IMP);

    const int tid = threadIdx.x;
    const int bb  = blockIdx.x >> 4;               // 16 blocks per batch
    const int s0  = (blockIdx.x & 15) * TPB;

    for (int i = tid; i < N_TOT; i += NTHREADS) w_local[i] = 0.0f;
    impS[tid] = imp[bb * SEQ + s0 + tid];

    // ---- GEMM1: H[128 tok][64] = X[128][1024] @ W[1024][64] + b ----
    const int tx = tid & 7;     // n-octet
    const int ty = tid >> 3;    // token-octet (token pairs ty*4..ty*4+3)

    ull acc[4][8];
    #pragma unroll
    for (int u = 0; u < 4; u++)
        #pragma unroll
        for (int j = 0; j < 8; j++) acc[u][j] = 0ull;

    const float4* Xg = (const float4*)(x + (size_t)(bb * SEQ + s0) * DMODEL);
    const float4* Ws4 = (const float4*)Ws;

    for (int p = 0; p < 8; p++) {
        __syncthreads();
        // load XsP: token-pair packed f32x2, [tp][128 d] (stride 130)
        for (int i = tid; i < 64 * 32; i += NTHREADS) {
            int tp = i >> 5, dq = i & 31;
            float4 fa = Xg[(size_t)(2*tp)   * 256 + p*32 + dq];
            float4 fb = Xg[(size_t)(2*tp+1) * 256 + p*32 + dq];
            ull* dst = XsP + (size_t)tp * XSP_STRIDE + dq * 4;
            dst[0] = d_pack(fa.x, fb.x);
            dst[1] = d_pack(fa.y, fb.y);
            dst[2] = d_pack(fa.z, fb.z);
            dst[3] = d_pack(fa.w, fb.w);
        }
        // load Ws chunk [128][64]
        {
            const float4* Wg = (const float4*)(Wm + (size_t)p * 128 * DSPACE);
            float4* d4 = (float4*)Ws;
            for (int i = tid; i < 2048; i += NTHREADS) d4[i] = Wg[i];
        }
        __syncthreads();

        const ull* xrow = XsP + (size_t)(ty * 4) * XSP_STRIDE;
        #pragma unroll 4
        for (int d = 0; d < 128; d++) {
            float4 b0 = Ws4[d * 16 + tx * 2];
            float4 b1 = Ws4[d * 16 + tx * 2 + 1];
            ull bd[8];
            bd[0]=d_dup(b0.x); bd[1]=d_dup(b0.y); bd[2]=d_dup(b0.z); bd[3]=d_dup(b0.w);
            bd[4]=d_dup(b1.x); bd[5]=d_dup(b1.y); bd[6]=d_dup(b1.z); bd[7]=d_dup(b1.w);
            ull a0 = xrow[d];
            ull a1 = xrow[XSP_STRIDE + d];
            ull a2 = xrow[2*XSP_STRIDE + d];
            ull a3 = xrow[3*XSP_STRIDE + d];
            #pragma unroll
            for (int j = 0; j < 8; j++) {
                acc[0][j] = d_fma2(a0, bd[j], acc[0][j]);
                acc[1][j] = d_fma2(a1, bd[j], acc[1][j]);
                acc[2][j] = d_fma2(a2, bd[j], acc[2][j]);
                acc[3][j] = d_fma2(a3, bd[j], acc[3][j]);
            }
        }
    }
    // bias + store HsP (token-pair packed)
    {
        #pragma unroll
        for (int j = 0; j < 8; j++) {
            ull bj = d_dup(bias[tx * 8 + j]);
            #pragma unroll
            for (int u = 0; u < 4; u++) acc[u][j] = d_add2(acc[u][j], bj);
        }
        #pragma unroll
        for (int u = 0; u < 4; u++)
            #pragma unroll
            for (int j = 0; j < 8; j++)
                HsP[(size_t)(ty*4 + u) * HSP_STRIDE + tx*8 + j] = acc[u][j];
    }

    // ---- GEMM2 + softmax + routing per slice ----
    do_slice<N_QK, 0>(sm, tid);
    do_slice<N_V,  N_QK>(sm, tid);
    do_slice<N_REL, N_QK + N_V>(sm, tid);
    do_slice<N_VAL, N_QK + N_V + N_REL>(sm, tid);

    __syncthreads();
    for (int i = tid; i < N_TOT; i += NTHREADS)
        atomicAdd(&g_w[bb * N_TOT + i], w_local[i]);
}

// ---------------- top-k / sparsify / output ----------------
__global__ void final_kernel(float* __restrict__ out) {
    const int b    = blockIdx.x >> 2;
    const int task = blockIdx.x & 3;
    const int tid  = threadIdx.x;   // 256

    const int loT[4] = {0, N_QK, N_QK + N_V, N_QK + N_V + N_REL};
    const int nT[4]  = {N_QK, N_V, N_REL, N_VAL};
    const int kT[4]  = {K_QK, K_V, K_REL, K_VAL};
    const int lo = loT[task], n = nT[task], K = kT[task];

    __shared__ float ws[N_QK];
    __shared__ int flag[N_QK];

    for (int i = tid; i < n; i += 256) ws[i] = g_w[b * N_TOT + lo + i];
    __syncthreads();

    if (task == 0)
        for (int i = tid; i < n; i += 256) out[OFF_WQK + b * N_QK + i] = ws[i];
    if (task == 1)
        for (int i = tid; i < n; i += 256) out[OFF_WV + b * N_V + i] = ws[i];

    for (int i = tid; i < n; i += 256) {
        float wi = ws[i]; int r = 0;
        for (int j = 0; j < n; j++) {
            float wj = ws[j];
            r += (wj > wi) || (wj == wi && j < i);
        }
        flag[i] = (r < K) ? 1 : 0;
    }
    __syncthreads();

    if (task <= 1) {
        int base = (task == 0) ? (OFF_IDXQK + b * K_QK) : (OFF_IDXV + b * K_V);
        for (int i = tid; i < n; i += 256) {
            if (flag[i]) {
                int pos = 0;
                for (int j = 0; j < i; j++) pos += flag[j];
                out[base + pos] = (float)i;
            }
        }
    } else if (task == 2) {
        for (int i = tid; i < n; i += 256) {
            float v = flag[i] ? ws[i] : 0.0f;
            out[OFF_RWQ + b * N_REL + i] = v;
            out[OFF_RWK + b * N_REL + i] = v;
        }
    } else {
        for (int i = tid; i < n; i += 256)
            out[OFF_VW + b * N_VAL + i] = flag[i] ? ws[i] : 0.0f;
    }
}

extern "C" void kernel_launch(void* const* d_in, const int* in_sizes, int n_in,
                              void* d_out, int out_size) {
    const float* x    = (const float*)d_in[0];
    const float* imp  = (const float*)d_in[1];
    const float* Wm   = (const float*)d_in[2];
    const float* bias = (const float*)d_in[3];
    const float* emb  = (const float*)d_in[4];
    float* out = (float*)d_out;

    cudaFuncSetAttribute(main_kernel, cudaFuncAttributeMaxDynamicSharedMemorySize, SMEM_BYTES);

    zero_w_kernel<<<(BATCH * N_TOT + 255) / 256, 256>>>();
    prep_kernel<<<N_TOT, 64>>>(emb);
    main_kernel<<<NBLOCKS, NTHREADS, SMEM_BYTES>>>(x, imp, Wm, bias);
    final_kernel<<<BATCH * 4, 256>>>(out);
}